// round 4
// baseline (speedup 1.0000x reference)
#include <cuda_runtime.h>
#include <cuda_bf16.h>
#include <cstdint>
#include <cstddef>

// ---------------------------------------------------------------------------
// QuantizedLinear via int8 mma.sync (base sm_100 ISA; tcgen05 unavailable:
// harness PTX target is compute_100 without the 'a' feature set).
//
// out[m,n] = acc[m,n]*alpha[n] + beta[n]
//   acc   = sum_k q(x[m,k]) * w[n,k]            (exact s32)
//   q(x)  = clamp(rint(x/sa + zp), -128, 127)
//   alpha = ws[n]*sa ; beta = bias[n] - zp*(sum_k w[n,k])*alpha
//
// R3 (= R2 resubmit after infra failure):
//     CTA tile 128x256, 8 warps of 64x64, single-barrier 4-stage cp.async
//     pipeline, K chunks of 64 B, fused epilogue.
// ---------------------------------------------------------------------------

#define K_DIM    1024
#define N_DIM    1024
#define M_MAX    16384
#define M_TILE   128
#define N_TILE   256
#define K_TILE   64
#define K_CHUNKS (K_DIM / K_TILE)        // 16
#define STAGES   4
#define THREADS  256

#define SMEM_STRIDE 80                    // 64B row + 16B pad (conflict-free quads)
#define A_BYTES   (M_TILE * SMEM_STRIDE)  // 10240
#define B_BYTES   (N_TILE * SMEM_STRIDE)  // 20480
#define STAGE_BYTES (A_BYTES + B_BYTES)   // 30720
#define SMEM_TOTAL (STAGES * STAGE_BYTES) // 122880  (1 CTA/SM)

__device__ __align__(16) int8_t g_A[(size_t)M_MAX * K_DIM];  // 16 MB
__device__ __align__(16) int8_t g_W[(size_t)N_DIM * K_DIM];  //  1 MB
__device__ float g_alpha[N_DIM];
__device__ float g_beta[N_DIM];

// ------------------------------- PTX helpers -------------------------------

__device__ __forceinline__ uint32_t smem_u32(const void* p) {
    return (uint32_t)__cvta_generic_to_shared(p);
}
__device__ __forceinline__ void cp_async16(uint32_t dst, const void* src) {
    asm volatile("cp.async.cg.shared.global [%0], [%1], 16;"
                 :: "r"(dst), "l"(src) : "memory");
}
__device__ __forceinline__ void cp_commit() {
    asm volatile("cp.async.commit_group;" ::: "memory");
}
__device__ __forceinline__ void cp_wait2() {
    asm volatile("cp.async.wait_group 2;" ::: "memory");
}
__device__ __forceinline__ void mma_s8(int* c, uint32_t a0, uint32_t a1,
                                       uint32_t a2, uint32_t a3,
                                       uint32_t b0, uint32_t b1) {
    asm volatile(
        "mma.sync.aligned.m16n8k32.row.col.s32.s8.s8.s32 "
        "{%0,%1,%2,%3}, {%4,%5,%6,%7}, {%8,%9}, {%0,%1,%2,%3};"
        : "+r"(c[0]), "+r"(c[1]), "+r"(c[2]), "+r"(c[3])
        : "r"(a0), "r"(a1), "r"(a2), "r"(a3), "r"(b0), "r"(b1));
}
__device__ __forceinline__ uint32_t lds32(uint32_t addr) {
    uint32_t v;
    asm volatile("ld.shared.b32 %0, [%1];" : "=r"(v) : "r"(addr));
    return v;
}

// --------------------------- Pass 1a: quantize x ---------------------------
// mul-then-add (no FMA contraction) to match jnp; rintf = round-half-even.
// x is single-use: load with evict-first (.cs) so g_A keeps L2 for the GEMM.

__global__ void quantize_kernel(const float* __restrict__ x,
                                const float* __restrict__ act_scale,
                                const float* __restrict__ act_zp,
                                int n4) {
    float inv = 1.0f / act_scale[0];
    float zp  = act_zp[0];
    int stride = gridDim.x * blockDim.x;
    for (int i = blockIdx.x * blockDim.x + threadIdx.x; i < n4; i += stride) {
        float4 v;
        asm volatile("ld.global.cs.v4.f32 {%0,%1,%2,%3}, [%4];"
                     : "=f"(v.x), "=f"(v.y), "=f"(v.z), "=f"(v.w)
                     : "l"(reinterpret_cast<const float4*>(x) + i));
        int q0 = (int)fminf(fmaxf(rintf(__fadd_rn(__fmul_rn(v.x, inv), zp)), -128.f), 127.f);
        int q1 = (int)fminf(fmaxf(rintf(__fadd_rn(__fmul_rn(v.y, inv), zp)), -128.f), 127.f);
        int q2 = (int)fminf(fmaxf(rintf(__fadd_rn(__fmul_rn(v.z, inv), zp)), -128.f), 127.f);
        int q3 = (int)fminf(fmaxf(rintf(__fadd_rn(__fmul_rn(v.w, inv), zp)), -128.f), 127.f);
        uint32_t p = (uint32_t)(q0 & 0xFF) | ((uint32_t)(q1 & 0xFF) << 8) |
                     ((uint32_t)(q2 & 0xFF) << 16) | ((uint32_t)(q3 & 0xFF) << 24);
        reinterpret_cast<uint32_t*>(g_A)[i] = p;
    }
}

// ------------------------- Pass 1b: weight prep ----------------------------

__global__ void prep_weights_kernel(const int* __restrict__ w,
                                    const float* __restrict__ wscales,
                                    const float* __restrict__ ascale,
                                    const float* __restrict__ azp,
                                    const float* __restrict__ bias) {
    int o = blockIdx.x;          // 0..1023
    int t = threadIdx.x;         // 0..127
    const int* row = w + (size_t)o * K_DIM;
    float sum = 0.f;
    for (int i = t * 4; i < K_DIM; i += 128 * 4) {
        int4 v = *reinterpret_cast<const int4*>(row + i);
        sum += (float)(v.x + v.y + v.z + v.w);
        uint32_t p = (uint32_t)(v.x & 0xFF) | ((uint32_t)(v.y & 0xFF) << 8) |
                     ((uint32_t)(v.z & 0xFF) << 16) | ((uint32_t)(v.w & 0xFF) << 24);
        reinterpret_cast<uint32_t*>(g_W + (size_t)o * K_DIM + i)[0] = p;
    }
    __shared__ float red[128];
    red[t] = sum;
    __syncthreads();
    for (int s = 64; s > 0; s >>= 1) {
        if (t < s) red[t] += red[t + s];
        __syncthreads();
    }
    if (t == 0) {
        float alpha = wscales[o] * ascale[0];
        g_alpha[o] = alpha;
        g_beta[o]  = bias[o] - azp[0] * red[0] * alpha;
    }
}

// ----------------------------- Pass 2: GEMM --------------------------------
// 8 warps in 2(M) x 4(N); warp tile 64 x 64.
// mma m16n8k32 fragments (g = lane>>2, q = lane&3):
//   A a0:(row g, k 4q) a1:(g+8, 4q) a2:(g, 16+4q) a3:(g+8, 16+4q)
//   B b0:(col g, k 4q) b1:(col g, k 16+4q)
//   C c0,c1:(row g, col 2q,2q+1)  c2,c3:(row g+8, ...)

__global__ __launch_bounds__(THREADS, 1)
void gemm_kernel(float* __restrict__ out) {
    extern __shared__ char smem[];
    uint32_t sbase = smem_u32(smem);

    const int tid  = threadIdx.x;
    const int wid  = tid >> 5;
    const int lane = tid & 31;
    const int g = lane >> 2;
    const int q = lane & 3;

    const int bid = blockIdx.x;
    const int m0 = (bid >> 2) * M_TILE;       // 128 m-tiles
    const int n0 = (bid & 3) * N_TILE;        // 4 n-tiles

    const int wm = wid & 1;                   // 0..1
    const int wn = wid >> 1;                  // 0..3

    // ---- per-thread cp.async job table: 6 x 16B chunks per stage ----
    // chunks 0..511 -> A (128 rows x 4), 512..1535 -> B (256 rows x 4)
    const int8_t* src[6];
    uint32_t dst[6];
#pragma unroll
    for (int j = 0; j < 6; j++) {
        int c = tid + j * THREADS;
        if (c < 512) {
            int r = c >> 2, t = c & 3;
            src[j] = g_A + (size_t)(m0 + r) * K_DIM + t * 16;
            dst[j] = (uint32_t)(r * SMEM_STRIDE + t * 16);
        } else {
            int cc = c - 512;
            int r = cc >> 2, t = cc & 3;
            src[j] = g_W + (size_t)(n0 + r) * K_DIM + t * 16;
            dst[j] = (uint32_t)(A_BYTES + r * SMEM_STRIDE + t * 16);
        }
    }
    auto load_chunk = [&](int kc) {
        uint32_t stage = sbase + (uint32_t)(kc & (STAGES - 1)) * STAGE_BYTES;
#pragma unroll
        for (int j = 0; j < 6; j++)
            cp_async16(stage + dst[j], src[j] + kc * K_TILE);
    };

    // prologue: stages 0..2
#pragma unroll
    for (int k = 0; k < STAGES - 1; k++) { load_chunk(k); cp_commit(); }

    int acc[4][8][4];
#pragma unroll
    for (int mf = 0; mf < 4; mf++)
#pragma unroll
        for (int nf = 0; nf < 8; nf++)
#pragma unroll
            for (int i = 0; i < 4; i++) acc[mf][nf][i] = 0;

    const uint32_t a_row0 = (uint32_t)((wm * 64 + g) * SMEM_STRIDE + 4 * q);
    const uint32_t b_col0 = (uint32_t)(A_BYTES + (wn * 64 + g) * SMEM_STRIDE + 4 * q);

    for (int kc = 0; kc < K_CHUNKS; kc++) {
        cp_wait2();
        __syncthreads();

        // issue loads for stage kc+3 (writes stage (kc-1)%4: already consumed)
        int kl = kc + STAGES - 1;
        if (kl < K_CHUNKS) load_chunk(kl);
        cp_commit();                          // empty group at tail keeps count

        uint32_t stage = sbase + (uint32_t)(kc & (STAGES - 1)) * STAGE_BYTES;
#pragma unroll
        for (int ks = 0; ks < 2; ks++) {      // two k=32 steps per 64B chunk
            uint32_t ko = (uint32_t)(ks * 32);
            uint32_t a[4][4];
#pragma unroll
            for (int mf = 0; mf < 4; mf++) {
                uint32_t r = stage + a_row0 + (uint32_t)(mf * 16 * SMEM_STRIDE) + ko;
                a[mf][0] = lds32(r);
                a[mf][1] = lds32(r + 8 * SMEM_STRIDE);
                a[mf][2] = lds32(r + 16);
                a[mf][3] = lds32(r + 8 * SMEM_STRIDE + 16);
            }
#pragma unroll
            for (int nf = 0; nf < 8; nf++) {
                uint32_t bb = stage + b_col0 + (uint32_t)(nf * 8 * SMEM_STRIDE) + ko;
                uint32_t b0 = lds32(bb);
                uint32_t b1 = lds32(bb + 16);
#pragma unroll
                for (int mf = 0; mf < 4; mf++)
                    mma_s8(acc[mf][nf], a[mf][0], a[mf][1], a[mf][2], a[mf][3], b0, b1);
            }
        }
    }

    // ---- epilogue: y = acc*alpha[n] + beta[n], float2 stores ----
#pragma unroll
    for (int nf = 0; nf < 8; nf++) {
        int col = n0 + wn * 64 + nf * 8 + 2 * q;
        float2 al = *reinterpret_cast<const float2*>(&g_alpha[col]);
        float2 be = *reinterpret_cast<const float2*>(&g_beta[col]);
#pragma unroll
        for (int mf = 0; mf < 4; mf++) {
            int row = m0 + wm * 64 + mf * 16 + g;
            float2 v0, v1;
            v0.x = (float)acc[mf][nf][0] * al.x + be.x;
            v0.y = (float)acc[mf][nf][1] * al.y + be.y;
            v1.x = (float)acc[mf][nf][2] * al.x + be.x;
            v1.y = (float)acc[mf][nf][3] * al.y + be.y;
            *reinterpret_cast<float2*>(out + (size_t)row * N_DIM + col) = v0;
            *reinterpret_cast<float2*>(out + (size_t)(row + 8) * N_DIM + col) = v1;
        }
    }
}

// ------------------------------- launcher ----------------------------------

extern "C" void kernel_launch(void* const* d_in, const int* in_sizes, int n_in,
                              void* d_out, int out_size) {
    const float* x    = (const float*)d_in[0];   // [B,S,IN] fp32
    const int*   wint = (const int*)  d_in[1];   // [OUT,IN] int32
    const float* wsc  = (const float*)d_in[2];   // [OUT]
    const float* asc  = (const float*)d_in[3];   // [1]
    const float* azp  = (const float*)d_in[4];   // [1]
    const float* bias = (const float*)d_in[5];   // [OUT]
    float* out = (float*)d_out;

    int M  = in_sizes[0] / K_DIM;                // 16384
    int n4 = in_sizes[0] / 4;

    cudaFuncSetAttribute(gemm_kernel,
                         cudaFuncAttributeMaxDynamicSharedMemorySize, SMEM_TOTAL);

    quantize_kernel<<<2048, 256>>>(x, asc, azp, n4);
    prep_weights_kernel<<<N_DIM, 128>>>(wint, wsc, asc, azp, bias);
    gemm_kernel<<<(M / M_TILE) * (N_DIM / N_TILE), THREADS, SMEM_TOTAL>>>(out);
}

// round 5
// speedup vs baseline: 1.1251x; 1.1251x over previous
#include <cuda_runtime.h>
#include <cuda_bf16.h>
#include <cstdint>
#include <cstddef>

// ---------------------------------------------------------------------------
// QuantizedLinear via int8 mma.sync (base sm_100 ISA; tcgen05 rejected by the
// harness's compute_100 PTX target).
//
// out[m,n] = acc[m,n]*alpha[n] + beta[n]
//   acc   = sum_k q(x[m,k]) * w[n,k]            (exact s32)
//   q(x)  = clamp(rint(x/sa + zp), -128, 127)
//   alpha = ws[n]*sa ; beta = bias[n] - zp*(sum_k w[n,k])*alpha
//
// R4: GEMM is mma.sync-issue-rate bound (R1/R3 tiling changes were neutral).
//     -> 128x128 CTA tiles, grid 1024, 2 CTAs/SM (launch_bounds(256,2)),
//        4 warps/SMSP for latency hiding, fine-grained tail.
// ---------------------------------------------------------------------------

#define K_DIM    1024
#define N_DIM    1024
#define M_MAX    16384
#define M_TILE   128
#define N_TILE   128
#define K_TILE   64
#define K_CHUNKS (K_DIM / K_TILE)        // 16
#define STAGES   4
#define THREADS  256

#define SMEM_STRIDE 80                    // 64B row + 16B pad (conflict-free quads)
#define A_BYTES   (M_TILE * SMEM_STRIDE)  // 10240
#define B_BYTES   (N_TILE * SMEM_STRIDE)  // 10240
#define STAGE_BYTES (A_BYTES + B_BYTES)   // 20480
#define SMEM_TOTAL (STAGES * STAGE_BYTES) // 81920 per CTA (2 CTAs/SM -> 160KB)

__device__ __align__(16) int8_t g_A[(size_t)M_MAX * K_DIM];  // 16 MB
__device__ __align__(16) int8_t g_W[(size_t)N_DIM * K_DIM];  //  1 MB
__device__ float g_alpha[N_DIM];
__device__ float g_beta[N_DIM];

// ------------------------------- PTX helpers -------------------------------

__device__ __forceinline__ uint32_t smem_u32(const void* p) {
    return (uint32_t)__cvta_generic_to_shared(p);
}
__device__ __forceinline__ void cp_async16(uint32_t dst, const void* src) {
    asm volatile("cp.async.cg.shared.global [%0], [%1], 16;"
                 :: "r"(dst), "l"(src) : "memory");
}
__device__ __forceinline__ void cp_commit() {
    asm volatile("cp.async.commit_group;" ::: "memory");
}
__device__ __forceinline__ void cp_wait2() {
    asm volatile("cp.async.wait_group 2;" ::: "memory");
}
__device__ __forceinline__ void mma_s8(int* c, uint32_t a0, uint32_t a1,
                                       uint32_t a2, uint32_t a3,
                                       uint32_t b0, uint32_t b1) {
    asm volatile(
        "mma.sync.aligned.m16n8k32.row.col.s32.s8.s8.s32 "
        "{%0,%1,%2,%3}, {%4,%5,%6,%7}, {%8,%9}, {%0,%1,%2,%3};"
        : "+r"(c[0]), "+r"(c[1]), "+r"(c[2]), "+r"(c[3])
        : "r"(a0), "r"(a1), "r"(a2), "r"(a3), "r"(b0), "r"(b1));
}
__device__ __forceinline__ uint32_t lds32(uint32_t addr) {
    uint32_t v;
    asm volatile("ld.shared.b32 %0, [%1];" : "=r"(v) : "r"(addr));
    return v;
}

// --------------------------- Pass 1a: quantize x ---------------------------
// mul-then-add (no FMA contraction) to match jnp; rintf = round-half-even.
// 32 B per thread per iteration (MLP=2). x single-use -> evict-first loads.

__global__ void quantize_kernel(const float* __restrict__ x,
                                const float* __restrict__ act_scale,
                                const float* __restrict__ act_zp,
                                int n8) {
    float inv = 1.0f / act_scale[0];
    float zp  = act_zp[0];
    int stride = gridDim.x * blockDim.x;
    for (int i = blockIdx.x * blockDim.x + threadIdx.x; i < n8; i += stride) {
        const float4* p = reinterpret_cast<const float4*>(x) + 2 * (size_t)i;
        float4 v0, v1;
        asm volatile("ld.global.cs.v4.f32 {%0,%1,%2,%3}, [%4];"
                     : "=f"(v0.x), "=f"(v0.y), "=f"(v0.z), "=f"(v0.w) : "l"(p));
        asm volatile("ld.global.cs.v4.f32 {%0,%1,%2,%3}, [%4];"
                     : "=f"(v1.x), "=f"(v1.y), "=f"(v1.z), "=f"(v1.w) : "l"(p + 1));
        int q0 = (int)fminf(fmaxf(rintf(__fadd_rn(__fmul_rn(v0.x, inv), zp)), -128.f), 127.f);
        int q1 = (int)fminf(fmaxf(rintf(__fadd_rn(__fmul_rn(v0.y, inv), zp)), -128.f), 127.f);
        int q2 = (int)fminf(fmaxf(rintf(__fadd_rn(__fmul_rn(v0.z, inv), zp)), -128.f), 127.f);
        int q3 = (int)fminf(fmaxf(rintf(__fadd_rn(__fmul_rn(v0.w, inv), zp)), -128.f), 127.f);
        int q4 = (int)fminf(fmaxf(rintf(__fadd_rn(__fmul_rn(v1.x, inv), zp)), -128.f), 127.f);
        int q5 = (int)fminf(fmaxf(rintf(__fadd_rn(__fmul_rn(v1.y, inv), zp)), -128.f), 127.f);
        int q6 = (int)fminf(fmaxf(rintf(__fadd_rn(__fmul_rn(v1.z, inv), zp)), -128.f), 127.f);
        int q7 = (int)fminf(fmaxf(rintf(__fadd_rn(__fmul_rn(v1.w, inv), zp)), -128.f), 127.f);
        uint2 pck;
        pck.x = (uint32_t)(q0 & 0xFF) | ((uint32_t)(q1 & 0xFF) << 8) |
                ((uint32_t)(q2 & 0xFF) << 16) | ((uint32_t)(q3 & 0xFF) << 24);
        pck.y = (uint32_t)(q4 & 0xFF) | ((uint32_t)(q5 & 0xFF) << 8) |
                ((uint32_t)(q6 & 0xFF) << 16) | ((uint32_t)(q7 & 0xFF) << 24);
        reinterpret_cast<uint2*>(g_A)[i] = pck;
    }
}

// ------------------------- Pass 1b: weight prep ----------------------------

__global__ void prep_weights_kernel(const int* __restrict__ w,
                                    const float* __restrict__ wscales,
                                    const float* __restrict__ ascale,
                                    const float* __restrict__ azp,
                                    const float* __restrict__ bias) {
    int o = blockIdx.x;          // 0..1023
    int t = threadIdx.x;         // 0..127
    const int* row = w + (size_t)o * K_DIM;
    float sum = 0.f;
    for (int i = t * 4; i < K_DIM; i += 128 * 4) {
        int4 v = *reinterpret_cast<const int4*>(row + i);
        sum += (float)(v.x + v.y + v.z + v.w);
        uint32_t p = (uint32_t)(v.x & 0xFF) | ((uint32_t)(v.y & 0xFF) << 8) |
                     ((uint32_t)(v.z & 0xFF) << 16) | ((uint32_t)(v.w & 0xFF) << 24);
        reinterpret_cast<uint32_t*>(g_W + (size_t)o * K_DIM + i)[0] = p;
    }
    __shared__ float red[128];
    red[t] = sum;
    __syncthreads();
    for (int s = 64; s > 0; s >>= 1) {
        if (t < s) red[t] += red[t + s];
        __syncthreads();
    }
    if (t == 0) {
        float alpha = wscales[o] * ascale[0];
        g_alpha[o] = alpha;
        g_beta[o]  = bias[o] - azp[0] * red[0] * alpha;
    }
}

// ----------------------------- Pass 2: GEMM --------------------------------
// CTA 128x128; 8 warps in 2(M) x 4(N); warp tile 64 x 32.
// mma m16n8k32 fragments (g = lane>>2, q = lane&3):
//   A a0:(row g, k 4q) a1:(g+8, 4q) a2:(g, 16+4q) a3:(g+8, 16+4q)
//   B b0:(col g, k 4q) b1:(col g, k 16+4q)
//   C c0,c1:(row g, col 2q,2q+1)  c2,c3:(row g+8, ...)

__global__ __launch_bounds__(THREADS, 2)
void gemm_kernel(float* __restrict__ out) {
    extern __shared__ char smem[];
    uint32_t sbase = smem_u32(smem);

    const int tid  = threadIdx.x;
    const int wid  = tid >> 5;
    const int lane = tid & 31;
    const int g = lane >> 2;
    const int q = lane & 3;

    const int bid = blockIdx.x;
    const int m0 = (bid >> 3) * M_TILE;       // 128 m-tiles
    const int n0 = (bid & 7) * N_TILE;        // 8 n-tiles

    const int wm = wid & 1;                   // 0..1 (64 rows each)
    const int wn = wid >> 1;                  // 0..3 (32 cols each)

    // ---- per-thread cp.async job table: 4 x 16B chunks per stage ----
    // chunks 0..511 -> A (128 rows x 4), 512..1023 -> B (128 rows x 4)
    const int8_t* src[4];
    uint32_t dst[4];
#pragma unroll
    for (int j = 0; j < 4; j++) {
        int c = tid + j * THREADS;
        if (c < 512) {
            int r = c >> 2, t = c & 3;
            src[j] = g_A + (size_t)(m0 + r) * K_DIM + t * 16;
            dst[j] = (uint32_t)(r * SMEM_STRIDE + t * 16);
        } else {
            int cc = c - 512;
            int r = cc >> 2, t = cc & 3;
            src[j] = g_W + (size_t)(n0 + r) * K_DIM + t * 16;
            dst[j] = (uint32_t)(A_BYTES + r * SMEM_STRIDE + t * 16);
        }
    }
    auto load_chunk = [&](int kc) {
        uint32_t stage = sbase + (uint32_t)(kc & (STAGES - 1)) * STAGE_BYTES;
#pragma unroll
        for (int j = 0; j < 4; j++)
            cp_async16(stage + dst[j], src[j] + kc * K_TILE);
    };

    // prologue: stages 0..2
#pragma unroll
    for (int k = 0; k < STAGES - 1; k++) { load_chunk(k); cp_commit(); }

    int acc[4][4][4];                          // [mf][nf][c]
#pragma unroll
    for (int mf = 0; mf < 4; mf++)
#pragma unroll
        for (int nf = 0; nf < 4; nf++)
#pragma unroll
            for (int i = 0; i < 4; i++) acc[mf][nf][i] = 0;

    const uint32_t a_row0 = (uint32_t)((wm * 64 + g) * SMEM_STRIDE + 4 * q);
    const uint32_t b_col0 = (uint32_t)(A_BYTES + (wn * 32 + g) * SMEM_STRIDE + 4 * q);

    for (int kc = 0; kc < K_CHUNKS; kc++) {
        cp_wait2();
        __syncthreads();

        // issue loads for stage kc+3 (writes stage (kc-1)%4: already consumed)
        int kl = kc + STAGES - 1;
        if (kl < K_CHUNKS) load_chunk(kl);
        cp_commit();                           // empty group at tail keeps count

        uint32_t stage = sbase + (uint32_t)(kc & (STAGES - 1)) * STAGE_BYTES;
#pragma unroll
        for (int ks = 0; ks < 2; ks++) {       // two k=32 steps per 64B chunk
            uint32_t ko = (uint32_t)(ks * 32);
            uint32_t a[4][4];
#pragma unroll
            for (int mf = 0; mf < 4; mf++) {
                uint32_t r = stage + a_row0 + (uint32_t)(mf * 16 * SMEM_STRIDE) + ko;
                a[mf][0] = lds32(r);
                a[mf][1] = lds32(r + 8 * SMEM_STRIDE);
                a[mf][2] = lds32(r + 16);
                a[mf][3] = lds32(r + 8 * SMEM_STRIDE + 16);
            }
#pragma unroll
            for (int nf = 0; nf < 4; nf++) {
                uint32_t bb = stage + b_col0 + (uint32_t)(nf * 8 * SMEM_STRIDE) + ko;
                uint32_t b0 = lds32(bb);
                uint32_t b1 = lds32(bb + 16);
#pragma unroll
                for (int mf = 0; mf < 4; mf++)
                    mma_s8(acc[mf][nf], a[mf][0], a[mf][1], a[mf][2], a[mf][3], b0, b1);
            }
        }
    }

    // ---- epilogue: y = acc*alpha[n] + beta[n], float2 stores ----
#pragma unroll
    for (int nf = 0; nf < 4; nf++) {
        int col = n0 + wn * 32 + nf * 8 + 2 * q;
        float2 al = *reinterpret_cast<const float2*>(&g_alpha[col]);
        float2 be = *reinterpret_cast<const float2*>(&g_beta[col]);
#pragma unroll
        for (int mf = 0; mf < 4; mf++) {
            int row = m0 + wm * 64 + mf * 16 + g;
            float2 v0, v1;
            v0.x = (float)acc[mf][nf][0] * al.x + be.x;
            v0.y = (float)acc[mf][nf][1] * al.y + be.y;
            v1.x = (float)acc[mf][nf][2] * al.x + be.x;
            v1.y = (float)acc[mf][nf][3] * al.y + be.y;
            *reinterpret_cast<float2*>(out + (size_t)row * N_DIM + col) = v0;
            *reinterpret_cast<float2*>(out + (size_t)(row + 8) * N_DIM + col) = v1;
        }
    }
}

// ------------------------------- launcher ----------------------------------

extern "C" void kernel_launch(void* const* d_in, const int* in_sizes, int n_in,
                              void* d_out, int out_size) {
    const float* x    = (const float*)d_in[0];   // [B,S,IN] fp32
    const int*   wint = (const int*)  d_in[1];   // [OUT,IN] int32
    const float* wsc  = (const float*)d_in[2];   // [OUT]
    const float* asc  = (const float*)d_in[3];   // [1]
    const float* azp  = (const float*)d_in[4];   // [1]
    const float* bias = (const float*)d_in[5];   // [OUT]
    float* out = (float*)d_out;

    int M  = in_sizes[0] / K_DIM;                // 16384
    int n8 = in_sizes[0] / 8;

    cudaFuncSetAttribute(gemm_kernel,
                         cudaFuncAttributeMaxDynamicSharedMemorySize, SMEM_TOTAL);

    quantize_kernel<<<2048, 256>>>(x, asc, azp, n8);
    prep_weights_kernel<<<N_DIM, 128>>>(wint, wsc, asc, azp, bias);
    gemm_kernel<<<(M / M_TILE) * (N_DIM / N_TILE), THREADS, SMEM_TOTAL>>>(out);
}

// round 6
// speedup vs baseline: 1.3117x; 1.1659x over previous
#include <cuda_runtime.h>
#include <cuda_bf16.h>
#include <cstdint>
#include <cstddef>

// ---------------------------------------------------------------------------
// QuantizedLinear via int8 mma.sync (base sm_100 ISA; tcgen05 rejected by the
// harness's compute_100 PTX target).
//
// out[m,n] = acc[m,n]*alpha[n] + beta[n]
//   acc   = sum_k q(x[m,k]) * w[n,k]            (exact s32)
//   q(x)  = clamp(rint(x/sa + zp), -128, 127)
//   alpha = ws[n]*sa ; beta = bias[n] - zp*(sum_k w[n,k])*alpha
//
// R5: GEMM mainloop fragment loads via ldmatrix.x4 (24 LDS -> 6 ldmatrix per
//     k32 step); quantize + weight prep merged into one launch.
//     Tiles: CTA 128x128, 2 CTAs/SM, 4-stage single-barrier cp.async pipe.
// ---------------------------------------------------------------------------

#define K_DIM    1024
#define N_DIM    1024
#define M_MAX    16384
#define M_TILE   128
#define N_TILE   128
#define K_TILE   64
#define K_CHUNKS (K_DIM / K_TILE)        // 16
#define STAGES   4
#define THREADS  256

#define SMEM_STRIDE 80                    // 64B row + 16B pad (conflict-free)
#define A_BYTES   (M_TILE * SMEM_STRIDE)  // 10240
#define B_BYTES   (N_TILE * SMEM_STRIDE)  // 10240
#define STAGE_BYTES (A_BYTES + B_BYTES)   // 20480
#define SMEM_TOTAL (STAGES * STAGE_BYTES) // 81920 per CTA (2 CTAs/SM)

#define QUANT_BLOCKS 2048

__device__ __align__(16) int8_t g_A[(size_t)M_MAX * K_DIM];  // 16 MB
__device__ __align__(16) int8_t g_W[(size_t)N_DIM * K_DIM];  //  1 MB
__device__ float g_alpha[N_DIM];
__device__ float g_beta[N_DIM];

// ------------------------------- PTX helpers -------------------------------

__device__ __forceinline__ uint32_t smem_u32(const void* p) {
    return (uint32_t)__cvta_generic_to_shared(p);
}
__device__ __forceinline__ void cp_async16(uint32_t dst, const void* src) {
    asm volatile("cp.async.cg.shared.global [%0], [%1], 16;"
                 :: "r"(dst), "l"(src) : "memory");
}
__device__ __forceinline__ void cp_commit() {
    asm volatile("cp.async.commit_group;" ::: "memory");
}
__device__ __forceinline__ void cp_wait2() {
    asm volatile("cp.async.wait_group 2;" ::: "memory");
}
__device__ __forceinline__ void mma_s8(int* c, const uint32_t* a,
                                       uint32_t b0, uint32_t b1) {
    asm volatile(
        "mma.sync.aligned.m16n8k32.row.col.s32.s8.s8.s32 "
        "{%0,%1,%2,%3}, {%4,%5,%6,%7}, {%8,%9}, {%0,%1,%2,%3};"
        : "+r"(c[0]), "+r"(c[1]), "+r"(c[2]), "+r"(c[3])
        : "r"(a[0]), "r"(a[1]), "r"(a[2]), "r"(a[3]), "r"(b0), "r"(b1));
}
__device__ __forceinline__ void ldsm_x4(uint32_t* r, uint32_t addr) {
    asm volatile("ldmatrix.sync.aligned.m8n8.x4.shared.b16 {%0,%1,%2,%3}, [%4];"
                 : "=r"(r[0]), "=r"(r[1]), "=r"(r[2]), "=r"(r[3]) : "r"(addr));
}

// ----------------- Pass 1 (merged): quantize x + weight prep ----------------
// blocks [0, QUANT_BLOCKS)          : quantize x -> g_A (s8)
// blocks [QUANT_BLOCKS, +N_DIM)     : one output channel each -> g_W, alpha/beta
// mul-then-add (no FMA contraction) matches jnp; rintf = round-half-even.

__global__ void prep_kernel(const float* __restrict__ x,
                            const float* __restrict__ act_scale,
                            const float* __restrict__ act_zp,
                            int n8,
                            const int* __restrict__ w,
                            const float* __restrict__ wscales,
                            const float* __restrict__ bias) {
    int tid = threadIdx.x;
    if (blockIdx.x < QUANT_BLOCKS) {
        float inv = 1.0f / act_scale[0];
        float zp  = act_zp[0];
        int stride = QUANT_BLOCKS * THREADS;
        for (int i = blockIdx.x * THREADS + tid; i < n8; i += stride) {
            const float4* p = reinterpret_cast<const float4*>(x) + 2 * (size_t)i;
            float4 v0, v1;
            asm volatile("ld.global.cs.v4.f32 {%0,%1,%2,%3}, [%4];"
                         : "=f"(v0.x), "=f"(v0.y), "=f"(v0.z), "=f"(v0.w) : "l"(p));
            asm volatile("ld.global.cs.v4.f32 {%0,%1,%2,%3}, [%4];"
                         : "=f"(v1.x), "=f"(v1.y), "=f"(v1.z), "=f"(v1.w) : "l"(p + 1));
            int q0 = (int)fminf(fmaxf(rintf(__fadd_rn(__fmul_rn(v0.x, inv), zp)), -128.f), 127.f);
            int q1 = (int)fminf(fmaxf(rintf(__fadd_rn(__fmul_rn(v0.y, inv), zp)), -128.f), 127.f);
            int q2 = (int)fminf(fmaxf(rintf(__fadd_rn(__fmul_rn(v0.z, inv), zp)), -128.f), 127.f);
            int q3 = (int)fminf(fmaxf(rintf(__fadd_rn(__fmul_rn(v0.w, inv), zp)), -128.f), 127.f);
            int q4 = (int)fminf(fmaxf(rintf(__fadd_rn(__fmul_rn(v1.x, inv), zp)), -128.f), 127.f);
            int q5 = (int)fminf(fmaxf(rintf(__fadd_rn(__fmul_rn(v1.y, inv), zp)), -128.f), 127.f);
            int q6 = (int)fminf(fmaxf(rintf(__fadd_rn(__fmul_rn(v1.z, inv), zp)), -128.f), 127.f);
            int q7 = (int)fminf(fmaxf(rintf(__fadd_rn(__fmul_rn(v1.w, inv), zp)), -128.f), 127.f);
            uint2 pck;
            pck.x = (uint32_t)(q0 & 0xFF) | ((uint32_t)(q1 & 0xFF) << 8) |
                    ((uint32_t)(q2 & 0xFF) << 16) | ((uint32_t)(q3 & 0xFF) << 24);
            pck.y = (uint32_t)(q4 & 0xFF) | ((uint32_t)(q5 & 0xFF) << 8) |
                    ((uint32_t)(q6 & 0xFF) << 16) | ((uint32_t)(q7 & 0xFF) << 24);
            reinterpret_cast<uint2*>(g_A)[i] = pck;
        }
    } else {
        int o = blockIdx.x - QUANT_BLOCKS;        // output channel
        const int* row = w + (size_t)o * K_DIM;
        int4 v = *reinterpret_cast<const int4*>(row + tid * 4);  // 256*4 = 1024
        float sum = (float)(v.x + v.y + v.z + v.w);
        uint32_t p = (uint32_t)(v.x & 0xFF) | ((uint32_t)(v.y & 0xFF) << 8) |
                     ((uint32_t)(v.z & 0xFF) << 16) | ((uint32_t)(v.w & 0xFF) << 24);
        reinterpret_cast<uint32_t*>(g_W + (size_t)o * K_DIM)[tid] = p;
        // reduce sum over 256 threads
        __shared__ float red[8];
#pragma unroll
        for (int s = 16; s > 0; s >>= 1)
            sum += __shfl_xor_sync(0xFFFFFFFFu, sum, s);
        if ((tid & 31) == 0) red[tid >> 5] = sum;
        __syncthreads();
        if (tid == 0) {
            float tot = 0.f;
#pragma unroll
            for (int i = 0; i < 8; i++) tot += red[i];
            float alpha = wscales[o] * act_scale[0];
            g_alpha[o] = alpha;
            g_beta[o]  = bias[o] - act_zp[0] * tot * alpha;
        }
    }
}

// ----------------------------- Pass 2: GEMM --------------------------------
// CTA 128x128; 8 warps in 2(M) x 4(N); warp tile 64 x 32.
// Fragments via ldmatrix.m8n8.x4.b16:
//   A x4 -> {a0,a1,a2,a3} of one 16-row, k32 block:
//     lane address: row = mf*16 + (lane&15), koff = ks*32 + (lane>>4)*16
//   B x4 -> {b0,b1}(nf), {b0,b1}(nf+1):
//     lane address: col = np*16 + ((lane>>4)&1)*8 + (lane&7),
//                   koff = ks*32 + ((lane>>3)&1)*16

__global__ __launch_bounds__(THREADS, 2)
void gemm_kernel(float* __restrict__ out) {
    extern __shared__ char smem[];
    uint32_t sbase = smem_u32(smem);

    const int tid  = threadIdx.x;
    const int wid  = tid >> 5;
    const int lane = tid & 31;
    const int g = lane >> 2;
    const int q = lane & 3;

    const int bid = blockIdx.x;
    const int m0 = (bid >> 3) * M_TILE;       // 128 m-tiles
    const int n0 = (bid & 7) * N_TILE;        // 8 n-tiles

    const int wm = wid & 1;                   // 0..1 (64 rows each)
    const int wn = wid >> 1;                  // 0..3 (32 cols each)

    // ---- per-thread cp.async job table: 4 x 16B chunks per stage ----
    const int8_t* src[4];
    uint32_t dst[4];
#pragma unroll
    for (int j = 0; j < 4; j++) {
        int c = tid + j * THREADS;
        if (c < 512) {
            int r = c >> 2, t = c & 3;
            src[j] = g_A + (size_t)(m0 + r) * K_DIM + t * 16;
            dst[j] = (uint32_t)(r * SMEM_STRIDE + t * 16);
        } else {
            int cc = c - 512;
            int r = cc >> 2, t = cc & 3;
            src[j] = g_W + (size_t)(n0 + r) * K_DIM + t * 16;
            dst[j] = (uint32_t)(A_BYTES + r * SMEM_STRIDE + t * 16);
        }
    }
    auto load_chunk = [&](int kc) {
        uint32_t stage = sbase + (uint32_t)(kc & (STAGES - 1)) * STAGE_BYTES;
#pragma unroll
        for (int j = 0; j < 4; j++)
            cp_async16(stage + dst[j], src[j] + kc * K_TILE);
    };

    // prologue: stages 0..2
#pragma unroll
    for (int k = 0; k < STAGES - 1; k++) { load_chunk(k); cp_commit(); }

    int acc[4][4][4];                          // [mf][nf][c]
#pragma unroll
    for (int mf = 0; mf < 4; mf++)
#pragma unroll
        for (int nf = 0; nf < 4; nf++)
#pragma unroll
            for (int i = 0; i < 4; i++) acc[mf][nf][i] = 0;

    // ldmatrix per-lane invariant offsets
    const uint32_t inv_a = (uint32_t)((wm * 64 + (lane & 15)) * SMEM_STRIDE
                                      + ((lane >> 4) << 4));
    const uint32_t inv_b = (uint32_t)(A_BYTES
                                      + (wn * 32 + ((lane >> 4) & 1) * 8 + (lane & 7)) * SMEM_STRIDE
                                      + ((lane >> 3) & 1) * 16);

    for (int kc = 0; kc < K_CHUNKS; kc++) {
        cp_wait2();
        __syncthreads();

        // issue loads for stage kc+3 (writes stage (kc-1)%4: already consumed)
        int kl = kc + STAGES - 1;
        if (kl < K_CHUNKS) load_chunk(kl);
        cp_commit();                           // empty group at tail keeps count

        uint32_t stage = sbase + (uint32_t)(kc & (STAGES - 1)) * STAGE_BYTES;
#pragma unroll
        for (int ks = 0; ks < 2; ks++) {       // two k=32 steps per 64B chunk
            uint32_t ko = (uint32_t)(ks * 32);
            uint32_t a[4][4];
#pragma unroll
            for (int mf = 0; mf < 4; mf++)
                ldsm_x4(a[mf], stage + inv_a + (uint32_t)(mf * 16 * SMEM_STRIDE) + ko);
            uint32_t b[2][4];
#pragma unroll
            for (int np = 0; np < 2; np++)
                ldsm_x4(b[np], stage + inv_b + (uint32_t)(np * 16 * SMEM_STRIDE) + ko);
#pragma unroll
            for (int nf = 0; nf < 4; nf++) {
                uint32_t b0 = b[nf >> 1][(nf & 1) * 2];
                uint32_t b1 = b[nf >> 1][(nf & 1) * 2 + 1];
#pragma unroll
                for (int mf = 0; mf < 4; mf++)
                    mma_s8(acc[mf][nf], a[mf], b0, b1);
            }
        }
    }

    // ---- epilogue: y = acc*alpha[n] + beta[n], float2 stores ----
#pragma unroll
    for (int nf = 0; nf < 4; nf++) {
        int col = n0 + wn * 32 + nf * 8 + 2 * q;
        float2 al = *reinterpret_cast<const float2*>(&g_alpha[col]);
        float2 be = *reinterpret_cast<const float2*>(&g_beta[col]);
#pragma unroll
        for (int mf = 0; mf < 4; mf++) {
            int row = m0 + wm * 64 + mf * 16 + g;
            float2 v0, v1;
            v0.x = (float)acc[mf][nf][0] * al.x + be.x;
            v0.y = (float)acc[mf][nf][1] * al.y + be.y;
            v1.x = (float)acc[mf][nf][2] * al.x + be.x;
            v1.y = (float)acc[mf][nf][3] * al.y + be.y;
            *reinterpret_cast<float2*>(out + (size_t)row * N_DIM + col) = v0;
            *reinterpret_cast<float2*>(out + (size_t)(row + 8) * N_DIM + col) = v1;
        }
    }
}

// ------------------------------- launcher ----------------------------------

extern "C" void kernel_launch(void* const* d_in, const int* in_sizes, int n_in,
                              void* d_out, int out_size) {
    const float* x    = (const float*)d_in[0];   // [B,S,IN] fp32
    const int*   wint = (const int*)  d_in[1];   // [OUT,IN] int32
    const float* wsc  = (const float*)d_in[2];   // [OUT]
    const float* asc  = (const float*)d_in[3];   // [1]
    const float* azp  = (const float*)d_in[4];   // [1]
    const float* bias = (const float*)d_in[5];   // [OUT]
    float* out = (float*)d_out;

    int M  = in_sizes[0] / K_DIM;                // 16384
    int n8 = in_sizes[0] / 8;

    cudaFuncSetAttribute(gemm_kernel,
                         cudaFuncAttributeMaxDynamicSharedMemorySize, SMEM_TOTAL);

    prep_kernel<<<QUANT_BLOCKS + N_DIM, THREADS>>>(x, asc, azp, n8, wint, wsc, bias);
    gemm_kernel<<<(M / M_TILE) * (N_DIM / N_TILE), THREADS, SMEM_TOTAL>>>(out);
}

// round 7
// speedup vs baseline: 1.3462x; 1.0263x over previous
#include <cuda_runtime.h>
#include <cuda_bf16.h>
#include <cstdint>
#include <cstddef>

// ---------------------------------------------------------------------------
// QuantizedLinear via int8 mma.sync (base sm_100 ISA; tcgen05 rejected by the
// harness's compute_100 PTX target).
//
// out[m,n] = acc[m,n]*alpha[n] + beta[n]
//   acc   = sum_k q(x[m,k]) * w[n,k]            (exact s32)
//   q(x)  = clamp(rint(x/sa + zp), -128, 127)
//   alpha = ws[n]*sa ; beta = bias[n] - zp*(sum_k w[n,k])*alpha
//
// R7: tensor pipe was 48% busy with occ capped by regs -> attack exposed
//     latency, not occupancy:
//     - K_TILE=128 (8 barriers instead of 16; 64 MMAs per barrier)
//     - 3-stage cp.async pipeline, stride-144 rows (conflict-free ldmatrix)
//     - ping-pong A-fragment prefetch across k32 steps
//     CTA 128x128, 8 warps of 64x32, 2 CTAs/SM.
// ---------------------------------------------------------------------------

#define K_DIM    1024
#define N_DIM    1024
#define M_MAX    16384
#define M_TILE   128
#define N_TILE   128
#define K_TILE   128
#define K_CHUNKS (K_DIM / K_TILE)        // 8
#define STAGES   3
#define THREADS  256

#define SMEM_STRIDE 144                   // 128B row + 16B pad (conflict-free)
#define A_BYTES   (M_TILE * SMEM_STRIDE)  // 18432
#define B_BYTES   (N_TILE * SMEM_STRIDE)  // 18432
#define STAGE_BYTES (A_BYTES + B_BYTES)   // 36864
#define SMEM_TOTAL (STAGES * STAGE_BYTES) // 110592 per CTA (2 CTAs -> 221184)

#define QUANT_BLOCKS 2048

__device__ __align__(16) int8_t g_A[(size_t)M_MAX * K_DIM];  // 16 MB
__device__ __align__(16) int8_t g_W[(size_t)N_DIM * K_DIM];  //  1 MB
__device__ float g_alpha[N_DIM];
__device__ float g_beta[N_DIM];

// ------------------------------- PTX helpers -------------------------------

__device__ __forceinline__ uint32_t smem_u32(const void* p) {
    return (uint32_t)__cvta_generic_to_shared(p);
}
__device__ __forceinline__ void cp_async16(uint32_t dst, const void* src) {
    asm volatile("cp.async.cg.shared.global [%0], [%1], 16;"
                 :: "r"(dst), "l"(src) : "memory");
}
__device__ __forceinline__ void cp_commit() {
    asm volatile("cp.async.commit_group;" ::: "memory");
}
__device__ __forceinline__ void cp_wait1() {
    asm volatile("cp.async.wait_group 1;" ::: "memory");
}
__device__ __forceinline__ void mma_s8(int* c, const uint32_t* a,
                                       uint32_t b0, uint32_t b1) {
    asm volatile(
        "mma.sync.aligned.m16n8k32.row.col.s32.s8.s8.s32 "
        "{%0,%1,%2,%3}, {%4,%5,%6,%7}, {%8,%9}, {%0,%1,%2,%3};"
        : "+r"(c[0]), "+r"(c[1]), "+r"(c[2]), "+r"(c[3])
        : "r"(a[0]), "r"(a[1]), "r"(a[2]), "r"(a[3]), "r"(b0), "r"(b1));
}
__device__ __forceinline__ void ldsm_x4(uint32_t* r, uint32_t addr) {
    asm volatile("ldmatrix.sync.aligned.m8n8.x4.shared.b16 {%0,%1,%2,%3}, [%4];"
                 : "=r"(r[0]), "=r"(r[1]), "=r"(r[2]), "=r"(r[3]) : "r"(addr));
}

// ----------------- Pass 1 (merged): quantize x + weight prep ----------------
// blocks [0, QUANT_BLOCKS)      : quantize x -> g_A (s8)
// blocks [QUANT_BLOCKS, +N_DIM) : one output channel each -> g_W, alpha/beta
// mul-then-add (no FMA contraction) matches jnp; rintf = round-half-even.

__global__ void prep_kernel(const float* __restrict__ x,
                            const float* __restrict__ act_scale,
                            const float* __restrict__ act_zp,
                            int n8,
                            const int* __restrict__ w,
                            const float* __restrict__ wscales,
                            const float* __restrict__ bias) {
    int tid = threadIdx.x;
    if (blockIdx.x < QUANT_BLOCKS) {
        float inv = 1.0f / act_scale[0];
        float zp  = act_zp[0];
        int stride = QUANT_BLOCKS * THREADS;
        for (int i = blockIdx.x * THREADS + tid; i < n8; i += stride) {
            const float4* p = reinterpret_cast<const float4*>(x) + 2 * (size_t)i;
            float4 v0, v1;
            asm volatile("ld.global.cs.v4.f32 {%0,%1,%2,%3}, [%4];"
                         : "=f"(v0.x), "=f"(v0.y), "=f"(v0.z), "=f"(v0.w) : "l"(p));
            asm volatile("ld.global.cs.v4.f32 {%0,%1,%2,%3}, [%4];"
                         : "=f"(v1.x), "=f"(v1.y), "=f"(v1.z), "=f"(v1.w) : "l"(p + 1));
            int q0 = (int)fminf(fmaxf(rintf(__fadd_rn(__fmul_rn(v0.x, inv), zp)), -128.f), 127.f);
            int q1 = (int)fminf(fmaxf(rintf(__fadd_rn(__fmul_rn(v0.y, inv), zp)), -128.f), 127.f);
            int q2 = (int)fminf(fmaxf(rintf(__fadd_rn(__fmul_rn(v0.z, inv), zp)), -128.f), 127.f);
            int q3 = (int)fminf(fmaxf(rintf(__fadd_rn(__fmul_rn(v0.w, inv), zp)), -128.f), 127.f);
            int q4 = (int)fminf(fmaxf(rintf(__fadd_rn(__fmul_rn(v1.x, inv), zp)), -128.f), 127.f);
            int q5 = (int)fminf(fmaxf(rintf(__fadd_rn(__fmul_rn(v1.y, inv), zp)), -128.f), 127.f);
            int q6 = (int)fminf(fmaxf(rintf(__fadd_rn(__fmul_rn(v1.z, inv), zp)), -128.f), 127.f);
            int q7 = (int)fminf(fmaxf(rintf(__fadd_rn(__fmul_rn(v1.w, inv), zp)), -128.f), 127.f);
            uint2 pck;
            pck.x = (uint32_t)(q0 & 0xFF) | ((uint32_t)(q1 & 0xFF) << 8) |
                    ((uint32_t)(q2 & 0xFF) << 16) | ((uint32_t)(q3 & 0xFF) << 24);
            pck.y = (uint32_t)(q4 & 0xFF) | ((uint32_t)(q5 & 0xFF) << 8) |
                    ((uint32_t)(q6 & 0xFF) << 16) | ((uint32_t)(q7 & 0xFF) << 24);
            reinterpret_cast<uint2*>(g_A)[i] = pck;
        }
    } else {
        int o = blockIdx.x - QUANT_BLOCKS;        // output channel
        const int* row = w + (size_t)o * K_DIM;
        int4 v = *reinterpret_cast<const int4*>(row + tid * 4);  // 256*4 = 1024
        float sum = (float)(v.x + v.y + v.z + v.w);
        uint32_t p = (uint32_t)(v.x & 0xFF) | ((uint32_t)(v.y & 0xFF) << 8) |
                     ((uint32_t)(v.z & 0xFF) << 16) | ((uint32_t)(v.w & 0xFF) << 24);
        reinterpret_cast<uint32_t*>(g_W + (size_t)o * K_DIM)[tid] = p;
        __shared__ float red[8];
#pragma unroll
        for (int s = 16; s > 0; s >>= 1)
            sum += __shfl_xor_sync(0xFFFFFFFFu, sum, s);
        if ((tid & 31) == 0) red[tid >> 5] = sum;
        __syncthreads();
        if (tid == 0) {
            float tot = 0.f;
#pragma unroll
            for (int i = 0; i < 8; i++) tot += red[i];
            float alpha = wscales[o] * act_scale[0];
            g_alpha[o] = alpha;
            g_beta[o]  = bias[o] - act_zp[0] * tot * alpha;
        }
    }
}

// ----------------------------- Pass 2: GEMM --------------------------------
// CTA 128x128; 8 warps in 2(M) x 4(N); warp tile 64 x 32.
// ldmatrix.m8n8.x4 fragment addressing (per-lane), stride-144 rows:
//   A: row = wm*64 + mf*16 + (lane&15), koff = ks*32 + (lane>>4)*16
//   B: col = wn*32 + np*16 + ((lane>>4)&1)*8 + (lane&7),
//      koff = ks*32 + ((lane>>3)&1)*16
// Ping-pong A prefetch: A(ks+1) issued before MMA block of ks.

__global__ __launch_bounds__(THREADS, 2)
void gemm_kernel(float* __restrict__ out) {
    extern __shared__ char smem[];
    uint32_t sbase = smem_u32(smem);

    const int tid  = threadIdx.x;
    const int wid  = tid >> 5;
    const int lane = tid & 31;
    const int g = lane >> 2;
    const int q = lane & 3;

    const int bid = blockIdx.x;
    const int m0 = (bid >> 3) * M_TILE;       // 128 m-tiles
    const int n0 = (bid & 7) * N_TILE;        // 8 n-tiles

    const int wm = wid & 1;                   // 0..1 (64 rows)
    const int wn = wid >> 1;                  // 0..3 (32 cols)

    // ---- cp.async: 8 x 16B per thread per stage (4 A rows + 4 B rows) ----
    const int lrow = tid >> 3;                // 0..31
    const int lcol = (tid & 7) * 16;          // 0..112
    const int8_t* src_a = g_A + (size_t)(m0 + lrow) * K_DIM + lcol;
    const int8_t* src_b = g_W + (size_t)(n0 + lrow) * K_DIM + lcol;
    const uint32_t dst_a = (uint32_t)(lrow * SMEM_STRIDE + lcol);
    const uint32_t dst_b = dst_a + A_BYTES;

    auto load_chunk = [&](int kc, uint32_t stage) {
#pragma unroll
        for (int j = 0; j < 4; j++)
            cp_async16(stage + dst_a + j * 32 * SMEM_STRIDE,
                       src_a + kc * K_TILE + (size_t)j * 32 * K_DIM);
#pragma unroll
        for (int j = 0; j < 4; j++)
            cp_async16(stage + dst_b + j * 32 * SMEM_STRIDE,
                       src_b + kc * K_TILE + (size_t)j * 32 * K_DIM);
    };

    // prologue: stages 0,1
    load_chunk(0, sbase);
    cp_commit();
    load_chunk(1, sbase + STAGE_BYTES);
    cp_commit();

    int acc[4][4][4];                          // [mf][nf][c]
#pragma unroll
    for (int mf = 0; mf < 4; mf++)
#pragma unroll
        for (int nf = 0; nf < 4; nf++)
#pragma unroll
            for (int i = 0; i < 4; i++) acc[mf][nf][i] = 0;

    const uint32_t inv_a = (uint32_t)((wm * 64 + (lane & 15)) * SMEM_STRIDE
                                      + ((lane >> 4) << 4));
    const uint32_t inv_b = (uint32_t)(A_BYTES
                                      + (wn * 32 + ((lane >> 4) & 1) * 8 + (lane & 7)) * SMEM_STRIDE
                                      + ((lane >> 3) & 1) * 16);

    uint32_t afrag[2][4][4];
    int stage_idx = 0;

    for (int kc = 0; kc < K_CHUNKS; kc++) {
        cp_wait1();
        __syncthreads();

        // load stage kc+2 (overwrites stage consumed at kc-1)
        int kl = kc + 2;
        if (kl < K_CHUNKS) {
            int sl = stage_idx + 2;
            if (sl >= STAGES) sl -= STAGES;
            load_chunk(kl, sbase + (uint32_t)sl * STAGE_BYTES);
        }
        cp_commit();                           // empty group at tail keeps count

        uint32_t stage = sbase + (uint32_t)stage_idx * STAGE_BYTES;
        if (++stage_idx == STAGES) stage_idx = 0;

        // preload A fragments for ks=0
#pragma unroll
        for (int mf = 0; mf < 4; mf++)
            ldsm_x4(afrag[0][mf], stage + inv_a + (uint32_t)(mf * 16 * SMEM_STRIDE));

#pragma unroll
        for (int ks = 0; ks < 4; ks++) {       // four k=32 steps per chunk
            uint32_t ko = (uint32_t)(ks * 32);
            uint32_t b[2][4];
#pragma unroll
            for (int np = 0; np < 2; np++)
                ldsm_x4(b[np], stage + inv_b + (uint32_t)(np * 16 * SMEM_STRIDE) + ko);
            if (ks < 3) {                      // prefetch A for ks+1
#pragma unroll
                for (int mf = 0; mf < 4; mf++)
                    ldsm_x4(afrag[(ks + 1) & 1][mf],
                            stage + inv_a + (uint32_t)(mf * 16 * SMEM_STRIDE) + ko + 32);
            }
            const uint32_t (*a)[4] = afrag[ks & 1];
#pragma unroll
            for (int nf = 0; nf < 4; nf++) {
                uint32_t b0 = b[nf >> 1][(nf & 1) * 2];
                uint32_t b1 = b[nf >> 1][(nf & 1) * 2 + 1];
#pragma unroll
                for (int mf = 0; mf < 4; mf++)
                    mma_s8(acc[mf][nf], a[mf], b0, b1);
            }
        }
    }

    // ---- epilogue: y = acc*alpha[n] + beta[n], float2 stores ----
#pragma unroll
    for (int nf = 0; nf < 4; nf++) {
        int col = n0 + wn * 32 + nf * 8 + 2 * q;
        float2 al = *reinterpret_cast<const float2*>(&g_alpha[col]);
        float2 be = *reinterpret_cast<const float2*>(&g_beta[col]);
#pragma unroll
        for (int mf = 0; mf < 4; mf++) {
            int row = m0 + wm * 64 + mf * 16 + g;
            float2 v0, v1;
            v0.x = (float)acc[mf][nf][0] * al.x + be.x;
            v0.y = (float)acc[mf][nf][1] * al.y + be.y;
            v1.x = (float)acc[mf][nf][2] * al.x + be.x;
            v1.y = (float)acc[mf][nf][3] * al.y + be.y;
            *reinterpret_cast<float2*>(out + (size_t)row * N_DIM + col) = v0;
            *reinterpret_cast<float2*>(out + (size_t)(row + 8) * N_DIM + col) = v1;
        }
    }
}

// ------------------------------- launcher ----------------------------------

extern "C" void kernel_launch(void* const* d_in, const int* in_sizes, int n_in,
                              void* d_out, int out_size) {
    const float* x    = (const float*)d_in[0];   // [B,S,IN] fp32
    const int*   wint = (const int*)  d_in[1];   // [OUT,IN] int32
    const float* wsc  = (const float*)d_in[2];   // [OUT]
    const float* asc  = (const float*)d_in[3];   // [1]
    const float* azp  = (const float*)d_in[4];   // [1]
    const float* bias = (const float*)d_in[5];   // [OUT]
    float* out = (float*)d_out;

    int M  = in_sizes[0] / K_DIM;                // 16384
    int n8 = in_sizes[0] / 8;

    cudaFuncSetAttribute(gemm_kernel,
                         cudaFuncAttributeMaxDynamicSharedMemorySize, SMEM_TOTAL);

    prep_kernel<<<QUANT_BLOCKS + N_DIM, THREADS>>>(x, asc, azp, n8, wint, wsc, bias);
    gemm_kernel<<<(M / M_TILE) * (N_DIM / N_TILE), THREADS, SMEM_TOTAL>>>(out);
}